// round 2
// baseline (speedup 1.0000x reference)
#include <cuda_runtime.h>
#include <cstdint>

#define NMAX    100000
#define EMAX    3200000
#define IN_DIM  512
#define HID     16

// Scratch (allocation-free): __device__ globals.
__device__ float g_xw[(size_t)NMAX * HID];   // x @ W1            [N,16]
__device__ float g_h2[(size_t)NMAX];         // relu(h+b1) @ W2   [N]
__device__ int   g_cnt[NMAX];                // per-dst degree
__device__ int   g_rs [NMAX + 1];            // CSR row starts
__device__ int   g_cur[NMAX];                // scatter cursors
__device__ int2  g_edges[EMAX];              // (src, w-bits) grouped by dst
__device__ int   g_bsum[128];                // scan block sums

// ---------------------------------------------------------------------------
// zero degree counters
// ---------------------------------------------------------------------------
__global__ void k_zero_cnt(int n) {
    int i = blockIdx.x * blockDim.x + threadIdx.x;
    if (i < n) g_cnt[i] = 0;
}

// ---------------------------------------------------------------------------
// K1: g_xw = x @ W1   (thread per row, W1 in shared, packed f32x2 FMA)
// ---------------------------------------------------------------------------
__global__ void k_gemm1(const float* __restrict__ x,
                        const float* __restrict__ W1, int n) {
    __shared__ float sW[IN_DIM * HID];                 // 32 KB
    for (int i = threadIdx.x; i < IN_DIM * HID / 4; i += blockDim.x)
        ((float4*)sW)[i] = ((const float4*)W1)[i];
    __syncthreads();

    int row = blockIdx.x * blockDim.x + threadIdx.x;
    if (row >= n) return;

    unsigned long long acc[8];
#pragma unroll
    for (int q = 0; q < 8; ++q) acc[q] = 0ull;

    const float4* xr = (const float4*)(x + (size_t)row * IN_DIM);
#pragma unroll 2
    for (int k4 = 0; k4 < IN_DIM / 4; ++k4) {
        float4 v = xr[k4];
        float xs[4] = {v.x, v.y, v.z, v.w};
#pragma unroll
        for (int kk = 0; kk < 4; ++kk) {
            int k = k4 * 4 + kk;
            unsigned long long xx;
            asm("mov.b64 %0, {%1, %1};" : "=l"(xx) : "f"(xs[kk]));
            const ulonglong2* w2 = (const ulonglong2*)(sW + k * HID);
#pragma unroll
            for (int p = 0; p < 4; ++p) {
                ulonglong2 wv = w2[p];
                asm("fma.rn.f32x2 %0, %1, %2, %0;"
                    : "+l"(acc[2 * p])     : "l"(xx), "l"(wv.x));
                asm("fma.rn.f32x2 %0, %1, %2, %0;"
                    : "+l"(acc[2 * p + 1]) : "l"(xx), "l"(wv.y));
            }
        }
    }

    unsigned long long* o = (unsigned long long*)(g_xw + (size_t)row * HID);
#pragma unroll
    for (int q = 0; q < 8; ++q) o[q] = acc[q];
}

// ---------------------------------------------------------------------------
// CSR build: histogram, 3-phase exclusive scan, scatter
// ---------------------------------------------------------------------------
__global__ void k_hist(const int* __restrict__ dst, int E) {
    int e = blockIdx.x * blockDim.x + threadIdx.x;
    if (e < E) atomicAdd(g_cnt + __ldg(dst + e), 1);
}

__global__ void k_scanA(int n) {                       // block sums (1024/blk)
    __shared__ int sh[1024];
    int idx = blockIdx.x * 1024 + threadIdx.x;
    sh[threadIdx.x] = (idx < n) ? g_cnt[idx] : 0;
    __syncthreads();
#pragma unroll
    for (int off = 512; off > 0; off >>= 1) {
        if (threadIdx.x < off) sh[threadIdx.x] += sh[threadIdx.x + off];
        __syncthreads();
    }
    if (threadIdx.x == 0) g_bsum[blockIdx.x] = sh[0];
}

__global__ void k_scanB(int nb) {                      // scan block sums (1 blk)
    __shared__ int sh[128];
    int t = threadIdx.x;
    sh[t] = (t < nb) ? g_bsum[t] : 0;
    __syncthreads();
#pragma unroll
    for (int off = 1; off < 128; off <<= 1) {
        int add = (t >= off) ? sh[t - off] : 0;
        __syncthreads();
        sh[t] += add;
        __syncthreads();
    }
    g_bsum[t] = (t == 0) ? 0 : sh[t - 1];              // exclusive
}

__global__ void k_scanC(int n, int E) {                // local scan + offset
    __shared__ int sh[1024];
    int t = threadIdx.x;
    int idx = blockIdx.x * 1024 + t;
    int v = (idx < n) ? g_cnt[idx] : 0;
    sh[t] = v;
    __syncthreads();
#pragma unroll
    for (int off = 1; off < 1024; off <<= 1) {
        int add = (t >= off) ? sh[t - off] : 0;
        __syncthreads();
        sh[t] += add;
        __syncthreads();
    }
    int excl = sh[t] - v + g_bsum[blockIdx.x];
    if (idx < n) { g_rs[idx] = excl; g_cur[idx] = excl; }
    if (idx == 0) g_rs[n] = E;
}

__global__ void k_scatter(const int* __restrict__ src,
                          const int* __restrict__ dst,
                          const float* __restrict__ w, int E) {
    int e = blockIdx.x * blockDim.x + threadIdx.x;
    if (e >= E) return;
    int p = atomicAdd(g_cur + __ldg(dst + e), 1);
    g_edges[p] = make_int2(__ldg(src + e), __float_as_int(__ldg(w + e)));
}

// ---------------------------------------------------------------------------
// spmm1 + relu + layer2-matvec fused: warp per dst node.
//   acc[16] = sum_e w_e * xw[src_e]  ->  h2[d] = relu(acc+b1) . W2
// ---------------------------------------------------------------------------
__global__ void k_spmm1f(const float* __restrict__ b1,
                         const float* __restrict__ W2, int n) {
    int gw   = (blockIdx.x * blockDim.x + threadIdx.x) >> 5;
    int lane = threadIdx.x & 31;
    if (gw >= n) return;

    int start = __ldg(g_rs + gw), end = __ldg(g_rs + gw + 1);
    int part = lane & 3, slot = lane >> 2;               // 8 edges in flight

    float4 acc = make_float4(0.f, 0.f, 0.f, 0.f);
    for (int i = start + slot; i < end; i += 8) {
        int2 e = __ldg(g_edges + i);
        float we = __int_as_float(e.y);
        float4 v = __ldg(((const float4*)g_xw) + (size_t)e.x * 4 + part);
        acc.x += we * v.x; acc.y += we * v.y;
        acc.z += we * v.z; acc.w += we * v.w;
    }
    // reduce across the 8 edge-slots (lanes with equal lane&3)
#pragma unroll
    for (int off = 16; off >= 4; off >>= 1) {
        acc.x += __shfl_down_sync(0xffffffffu, acc.x, off);
        acc.y += __shfl_down_sync(0xffffffffu, acc.y, off);
        acc.z += __shfl_down_sync(0xffffffffu, acc.z, off);
        acc.w += __shfl_down_sync(0xffffffffu, acc.w, off);
    }
    float4 bv = __ldg(((const float4*)b1) + part);
    float4 wv = __ldg(((const float4*)W2) + part);
    float p = fmaxf(acc.x + bv.x, 0.f) * wv.x
            + fmaxf(acc.y + bv.y, 0.f) * wv.y
            + fmaxf(acc.z + bv.z, 0.f) * wv.z
            + fmaxf(acc.w + bv.w, 0.f) * wv.w;
    p += __shfl_down_sync(0xffffffffu, p, 2);
    p += __shfl_down_sync(0xffffffffu, p, 1);
    if (lane == 0) g_h2[gw] = p;
}

// ---------------------------------------------------------------------------
// spmm2: warp per dst node, scalar gather + warp reduce, writes out directly.
// ---------------------------------------------------------------------------
__global__ void k_spmm2f(const float* __restrict__ b2,
                         float* __restrict__ out, int n) {
    int gw   = (blockIdx.x * blockDim.x + threadIdx.x) >> 5;
    int lane = threadIdx.x & 31;
    if (gw >= n) return;

    int start = __ldg(g_rs + gw), end = __ldg(g_rs + gw + 1);
    float acc = 0.f;
    for (int i = start + lane; i < end; i += 32) {
        int2 e = __ldg(g_edges + i);
        acc += __int_as_float(e.y) * __ldg(g_h2 + e.x);
    }
#pragma unroll
    for (int off = 16; off > 0; off >>= 1)
        acc += __shfl_down_sync(0xffffffffu, acc, off);
    if (lane == 0) out[gw] = __ldg(b2) + acc;
}

// ---------------------------------------------------------------------------
extern "C" void kernel_launch(void* const* d_in, const int* in_sizes, int n_in,
                              void* d_out, int out_size) {
    const float* x   = (const float*)d_in[0];
    const int*   src = (const int*)  d_in[1];
    const int*   dst = (const int*)  d_in[2];
    const float* w   = (const float*)d_in[3];
    const float* W1  = (const float*)d_in[4];
    const float* b1  = (const float*)d_in[5];
    const float* W2  = (const float*)d_in[6];
    const float* b2  = (const float*)d_in[7];
    float* out = (float*)d_out;

    int N = in_sizes[0] / IN_DIM;
    int E = in_sizes[1];

    const int T = 256;
    int nb_scan = (N + 1023) / 1024;                    // <= 98 for N=100K

    k_zero_cnt<<<(N + T - 1) / T, T>>>(N);
    k_gemm1<<<(N + T - 1) / T, T>>>(x, W1, N);
    k_hist<<<(E + T - 1) / T, T>>>(dst, E);
    k_scanA<<<nb_scan, 1024>>>(N);
    k_scanB<<<1, 128>>>(nb_scan);
    k_scanC<<<nb_scan, 1024>>>(N, E);
    k_scatter<<<(E + T - 1) / T, T>>>(src, dst, w, E);

    int warps = N;                                      // warp per dst
    int blocks = (warps * 32 + T - 1) / T;
    k_spmm1f<<<blocks, T>>>(b1, W2, N);
    k_spmm2f<<<blocks, T>>>(b2, out, N);
}

// round 3
// speedup vs baseline: 1.1195x; 1.1195x over previous
#include <cuda_runtime.h>
#include <cstdint>

#define NMAX    100000
#define IN_DIM  512
#define HID     16

// Scratch (allocation-free per harness rules): __device__ globals.
__device__ float g_xw[(size_t)NMAX * HID];   // x @ W1           [N,16]
__device__ float g_h [(size_t)NMAX * HID];   // spmm accumulator [N,16]
__device__ float g_h2[(size_t)NMAX];         // relu(h+b1) @ W2  [N]

// ---------------------------------------------------------------------------
// K0a/K0b: zero the spmm-1 accumulator (split in two so spmm1 is the 4th
// launch in the graph -> it is the kernel ncu samples)
// ---------------------------------------------------------------------------
__global__ void k_zero_hA(int n4) {
    int i = blockIdx.x * blockDim.x + threadIdx.x;
    if (i < n4) ((float4*)g_h)[i] = make_float4(0.f, 0.f, 0.f, 0.f);
}
__global__ void k_zero_hB(int off, int n4) {
    int i = off + blockIdx.x * blockDim.x + threadIdx.x;
    if (i < n4) ((float4*)g_h)[i] = make_float4(0.f, 0.f, 0.f, 0.f);
}

// ---------------------------------------------------------------------------
// K1: g_xw = x @ W1   (thread per row, W1 in shared, packed f32x2 FMA)
// ---------------------------------------------------------------------------
__global__ void k_gemm1(const float* __restrict__ x,
                        const float* __restrict__ W1, int n) {
    __shared__ float sW[IN_DIM * HID];                 // 32 KB
    for (int i = threadIdx.x; i < IN_DIM * HID / 4; i += blockDim.x)
        ((float4*)sW)[i] = ((const float4*)W1)[i];
    __syncthreads();

    int row = blockIdx.x * blockDim.x + threadIdx.x;
    if (row >= n) return;

    unsigned long long acc[8];
#pragma unroll
    for (int q = 0; q < 8; ++q) acc[q] = 0ull;

    const float4* xr = (const float4*)(x + (size_t)row * IN_DIM);
#pragma unroll 2
    for (int k4 = 0; k4 < IN_DIM / 4; ++k4) {
        float4 v = xr[k4];
        float xs[4] = {v.x, v.y, v.z, v.w};
#pragma unroll
        for (int kk = 0; kk < 4; ++kk) {
            int k = k4 * 4 + kk;
            unsigned long long xx;
            asm("mov.b64 %0, {%1, %1};" : "=l"(xx) : "f"(xs[kk]));
            const ulonglong2* w2 = (const ulonglong2*)(sW + k * HID);
#pragma unroll
            for (int p = 0; p < 4; ++p) {
                ulonglong2 wv = w2[p];
                asm("fma.rn.f32x2 %0, %1, %2, %0;"
                    : "+l"(acc[2 * p])     : "l"(xx), "l"(wv.x));
                asm("fma.rn.f32x2 %0, %1, %2, %0;"
                    : "+l"(acc[2 * p + 1]) : "l"(xx), "l"(wv.y));
            }
        }
    }

    unsigned long long* o = (unsigned long long*)(g_xw + (size_t)row * HID);
#pragma unroll
    for (int q = 0; q < 8; ++q) o[q] = acc[q];
}

// ---------------------------------------------------------------------------
// K2: g_h[dst] += w * g_xw[src]   (2 threads/edge, 2x vector RED each)
// ---------------------------------------------------------------------------
__global__ void k_spmm1(const int*   __restrict__ src,
                        const int*   __restrict__ dst,
                        const float* __restrict__ w, int E) {
    int t = blockIdx.x * blockDim.x + threadIdx.x;
    int e = t >> 1;
    if (e >= E) return;
    int half = t & 1;

    int   s  = __ldg(src + e);
    int   d  = __ldg(dst + e);
    float we = __ldg(w   + e);

    const float4* g = ((const float4*)g_xw) + (((size_t)s) << 2) + (half << 1);
    float4 v0 = __ldg(g);
    float4 v1 = __ldg(g + 1);

    float a0 = v0.x * we, b0 = v0.y * we, c0 = v0.z * we, d0 = v0.w * we;
    float a1 = v1.x * we, b1 = v1.y * we, c1 = v1.z * we, d1 = v1.w * we;

    float* addr = g_h + (((size_t)d) << 4) + (half << 3);
    asm volatile("red.global.add.v4.f32 [%0], {%1, %2, %3, %4};"
                 :: "l"(addr), "f"(a0), "f"(b0), "f"(c0), "f"(d0) : "memory");
    asm volatile("red.global.add.v4.f32 [%0], {%1, %2, %3, %4};"
                 :: "l"(addr + 4), "f"(a1), "f"(b1), "f"(c1), "f"(d1) : "memory");
}

// ---------------------------------------------------------------------------
// K3: g_h2 = relu(g_h + b1) @ W2 ; out init to b2
// ---------------------------------------------------------------------------
__global__ void k_layer2a(const float* __restrict__ b1,
                          const float* __restrict__ W2,
                          const float* __restrict__ b2,
                          float* __restrict__ out, int n) {
    int i = blockIdx.x * blockDim.x + threadIdx.x;
    if (i >= n) return;
    float acc = 0.f;
#pragma unroll
    for (int p = 0; p < 4; ++p) {
        float4 hv = ((const float4*)g_h)[(size_t)i * 4 + p];
        float4 bv = __ldg(((const float4*)b1) + p);
        float4 wv = __ldg(((const float4*)W2) + p);
        acc += fmaxf(hv.x + bv.x, 0.f) * wv.x
             + fmaxf(hv.y + bv.y, 0.f) * wv.y
             + fmaxf(hv.z + bv.z, 0.f) * wv.z
             + fmaxf(hv.w + bv.w, 0.f) * wv.w;
    }
    g_h2[i] = acc;
    out[i]  = __ldg(b2);      // out starts at bias; K4 atomically accumulates
}

// ---------------------------------------------------------------------------
// K4: out[dst] += w * g_h2[src]   (scalar RED, 1 thread/edge)
// ---------------------------------------------------------------------------
__global__ void k_spmm2(const int*   __restrict__ src,
                        const int*   __restrict__ dst,
                        const float* __restrict__ w,
                        float* __restrict__ out, int E) {
    int e = blockIdx.x * blockDim.x + threadIdx.x;
    if (e >= E) return;
    atomicAdd(out + __ldg(dst + e), __ldg(w + e) * __ldg(g_h2 + __ldg(src + e)));
}

// ---------------------------------------------------------------------------
extern "C" void kernel_launch(void* const* d_in, const int* in_sizes, int n_in,
                              void* d_out, int out_size) {
    const float* x   = (const float*)d_in[0];
    const int*   src = (const int*)  d_in[1];
    const int*   dst = (const int*)  d_in[2];
    const float* w   = (const float*)d_in[3];
    const float* W1  = (const float*)d_in[4];
    const float* b1  = (const float*)d_in[5];
    const float* W2  = (const float*)d_in[6];
    const float* b2  = (const float*)d_in[7];
    float* out = (float*)d_out;

    int N = in_sizes[0] / IN_DIM;
    int E = in_sizes[1];

    const int T = 256;

    // K0 split in two halves (launch slots 1 and 2)
    int n4   = N * HID / 4;              // 400K float4
    int n4h  = n4 / 2;
    k_zero_hA<<<(n4h + T - 1) / T, T>>>(n4h);
    k_zero_hB<<<(n4 - n4h + T - 1) / T, T>>>(n4h, n4);

    // slot 3: gemm
    k_gemm1<<<(N + T - 1) / T, T>>>(x, W1, N);

    // slot 4 (ncu-sampled): spmm1, 2 threads/edge
    long long t2 = (long long)E * 2;
    k_spmm1<<<(unsigned)((t2 + 511) / 512), 512>>>(src, dst, w, E);

    // slot 5: h2 = relu(h + b1) @ W2 ; out = b2
    k_layer2a<<<(N + T - 1) / T, T>>>(b1, W2, b2, out, N);

    // slot 6: out += scatter(w * h2[src]) by dst
    k_spmm2<<<(E + 511) / 512, 512>>>(src, dst, w, out, E);
}

// round 4
// speedup vs baseline: 1.6038x; 1.4327x over previous
#include <cuda_runtime.h>
#include <cstdint>

#define NMAX    100000
#define IN_DIM  512
#define HID     16

typedef unsigned long long ull;

// Scratch (allocation-free per harness rules): __device__ globals.
__device__ float g_xw[(size_t)NMAX * HID];   // x @ W1           [N,16]
__device__ float g_h [(size_t)NMAX * HID];   // spmm accumulator [N,16]
__device__ float g_h2[(size_t)NMAX];         // relu(h+b1) @ W2  [N]

// ---------------------------------------------------------------------------
// K0a/b/c: zero the spmm-1 accumulator (3-way split so gemm1 is launch #4 ->
// it's the kernel ncu samples)
// ---------------------------------------------------------------------------
__global__ void k_zero(int off, int lim) {
    int i = off + blockIdx.x * blockDim.x + threadIdx.x;
    if (i < lim) ((float4*)g_h)[i] = make_float4(0.f, 0.f, 0.f, 0.f);
}

// ---------------------------------------------------------------------------
// K1: g_xw = x @ W1   (smem-tiled, 2 rows/thread, packed f32x2 FMA)
//   block = 128 threads -> 256 rows; K-tile = 32
// ---------------------------------------------------------------------------
#define KT      32
#define ROWS_B  256
#define PAD     36        // 32 + 4 floats padding (conflict-free LDS.128)

__global__ void __launch_bounds__(128) k_gemm1(
        const float* __restrict__ x,
        const float* __restrict__ W1, int n) {
    __shared__ float sX[ROWS_B * PAD];        // 36.9 KB
    __shared__ float sW[KT * HID];            // 2 KB

    int t    = threadIdx.x;                   // 0..127
    int row0 = blockIdx.x * ROWS_B;

    ull acc0[8], acc1[8];
#pragma unroll
    for (int q = 0; q < 8; ++q) { acc0[q] = 0ull; acc1[q] = 0ull; }

#pragma unroll 1
    for (int kt = 0; kt < IN_DIM / KT; ++kt) {
        // W slice: 32x16 floats = 128 float4, one per thread (coalesced)
        ((float4*)sW)[t] = __ldg(((const float4*)(W1 + kt * KT * HID)) + t);

        // x tile: 256 rows x 32 cols = 2048 float4, 16 per thread (coalesced)
#pragma unroll
        for (int i = 0; i < 16; ++i) {
            int flat = i * 128 + t;
            int r = flat >> 3, q = flat & 7;
            int grow = row0 + r;
            float4 v = make_float4(0.f, 0.f, 0.f, 0.f);
            if (grow < n)
                v = __ldg(((const float4*)(x + (size_t)grow * IN_DIM + kt * KT)) + q);
            *(float4*)(sX + r * PAD + q * 4) = v;
        }
        __syncthreads();

#pragma unroll
        for (int k4 = 0; k4 < KT / 4; ++k4) {
            float4 v0 = *(const float4*)(sX + t * PAD + k4 * 4);
            float4 v1 = *(const float4*)(sX + (t + 128) * PAD + k4 * 4);
            float xs0[4] = {v0.x, v0.y, v0.z, v0.w};
            float xs1[4] = {v1.x, v1.y, v1.z, v1.w};
#pragma unroll
            for (int kk = 0; kk < 4; ++kk) {
                const ulonglong2* wr =
                    (const ulonglong2*)(sW + (k4 * 4 + kk) * HID);
                ulonglong2 wa = wr[0], wb = wr[1];
                ull xx0, xx1;
                asm("mov.b64 %0, {%1, %1};" : "=l"(xx0) : "f"(xs0[kk]));
                asm("mov.b64 %0, {%1, %1};" : "=l"(xx1) : "f"(xs1[kk]));
                asm("fma.rn.f32x2 %0, %1, %2, %0;" : "+l"(acc0[0]) : "l"(xx0), "l"(wa.x));
                asm("fma.rn.f32x2 %0, %1, %2, %0;" : "+l"(acc0[1]) : "l"(xx0), "l"(wa.y));
                asm("fma.rn.f32x2 %0, %1, %2, %0;" : "+l"(acc0[2]) : "l"(xx0), "l"(wb.x));
                asm("fma.rn.f32x2 %0, %1, %2, %0;" : "+l"(acc0[3]) : "l"(xx0), "l"(wb.y));
                asm("fma.rn.f32x2 %0, %1, %2, %0;" : "+l"(acc1[0]) : "l"(xx1), "l"(wa.x));
                asm("fma.rn.f32x2 %0, %1, %2, %0;" : "+l"(acc1[1]) : "l"(xx1), "l"(wa.y));
                asm("fma.rn.f32x2 %0, %1, %2, %0;" : "+l"(acc1[2]) : "l"(xx1), "l"(wb.x));
                asm("fma.rn.f32x2 %0, %1, %2, %0;" : "+l"(acc1[3]) : "l"(xx1), "l"(wb.y));
                const ulonglong2* wr2 = wr + 2;
                ulonglong2 wc = wr2[0], wd = wr2[1];
                asm("fma.rn.f32x2 %0, %1, %2, %0;" : "+l"(acc0[4]) : "l"(xx0), "l"(wc.x));
                asm("fma.rn.f32x2 %0, %1, %2, %0;" : "+l"(acc0[5]) : "l"(xx0), "l"(wc.y));
                asm("fma.rn.f32x2 %0, %1, %2, %0;" : "+l"(acc0[6]) : "l"(xx0), "l"(wd.x));
                asm("fma.rn.f32x2 %0, %1, %2, %0;" : "+l"(acc0[7]) : "l"(xx0), "l"(wd.y));
                asm("fma.rn.f32x2 %0, %1, %2, %0;" : "+l"(acc1[4]) : "l"(xx1), "l"(wc.x));
                asm("fma.rn.f32x2 %0, %1, %2, %0;" : "+l"(acc1[5]) : "l"(xx1), "l"(wc.y));
                asm("fma.rn.f32x2 %0, %1, %2, %0;" : "+l"(acc1[6]) : "l"(xx1), "l"(wd.x));
                asm("fma.rn.f32x2 %0, %1, %2, %0;" : "+l"(acc1[7]) : "l"(xx1), "l"(wd.y));
            }
        }
        __syncthreads();
    }

    int r0 = row0 + t, r1 = row0 + t + 128;
    if (r0 < n) {
        ull* o = (ull*)(g_xw + (size_t)r0 * HID);
#pragma unroll
        for (int q = 0; q < 8; ++q) o[q] = acc0[q];
    }
    if (r1 < n) {
        ull* o = (ull*)(g_xw + (size_t)r1 * HID);
#pragma unroll
        for (int q = 0; q < 8; ++q) o[q] = acc1[q];
    }
}

// ---------------------------------------------------------------------------
// K2: g_h[dst] += w * g_xw[src]   (4 threads/edge = min wavefronts, 2-edge ILP)
// ---------------------------------------------------------------------------
__global__ void k_spmm1(const int*   __restrict__ src,
                        const int*   __restrict__ dst,
                        const float* __restrict__ w, int E, int half) {
    int t = blockIdx.x * blockDim.x + threadIdx.x;
    int i = t >> 2;
    if (i >= half) return;
    int part = t & 3;

    int e1 = i, e2 = i + half;
    bool has2 = (e2 < E);

    int   s1 = __ldg(src + e1);
    int   d1 = __ldg(dst + e1);
    float w1 = __ldg(w   + e1);
    int   s2 = has2 ? __ldg(src + e2) : 0;
    int   d2 = has2 ? __ldg(dst + e2) : 0;
    float w2 = has2 ? __ldg(w   + e2) : 0.f;

    float4 v1 = __ldg(((const float4*)g_xw) + (((size_t)s1) << 2) + part);
    float4 v2 = __ldg(((const float4*)g_xw) + (((size_t)s2) << 2) + part);

    float* a1 = g_h + (((size_t)d1) << 4) + (part << 2);
    asm volatile("red.global.add.v4.f32 [%0], {%1, %2, %3, %4};"
                 :: "l"(a1), "f"(v1.x * w1), "f"(v1.y * w1),
                    "f"(v1.z * w1), "f"(v1.w * w1) : "memory");
    if (has2) {
        float* a2 = g_h + (((size_t)d2) << 4) + (part << 2);
        asm volatile("red.global.add.v4.f32 [%0], {%1, %2, %3, %4};"
                     :: "l"(a2), "f"(v2.x * w2), "f"(v2.y * w2),
                        "f"(v2.z * w2), "f"(v2.w * w2) : "memory");
    }
}

// ---------------------------------------------------------------------------
// K3: g_h2 = relu(g_h + b1) @ W2 ; out init to b2
// ---------------------------------------------------------------------------
__global__ void k_layer2a(const float* __restrict__ b1,
                          const float* __restrict__ W2,
                          const float* __restrict__ b2,
                          float* __restrict__ out, int n) {
    int i = blockIdx.x * blockDim.x + threadIdx.x;
    if (i >= n) return;
    float acc = 0.f;
#pragma unroll
    for (int p = 0; p < 4; ++p) {
        float4 hv = ((const float4*)g_h)[(size_t)i * 4 + p];
        float4 bv = __ldg(((const float4*)b1) + p);
        float4 wv = __ldg(((const float4*)W2) + p);
        acc += fmaxf(hv.x + bv.x, 0.f) * wv.x
             + fmaxf(hv.y + bv.y, 0.f) * wv.y
             + fmaxf(hv.z + bv.z, 0.f) * wv.z
             + fmaxf(hv.w + bv.w, 0.f) * wv.w;
    }
    g_h2[i] = acc;
    out[i]  = __ldg(b2);
}

// ---------------------------------------------------------------------------
// K4: out[dst] += w * g_h2[src]   (scalar RED, 2-edge ILP)
// ---------------------------------------------------------------------------
__global__ void k_spmm2(const int*   __restrict__ src,
                        const int*   __restrict__ dst,
                        const float* __restrict__ w,
                        float* __restrict__ out, int E, int half) {
    int i = blockIdx.x * blockDim.x + threadIdx.x;
    if (i >= half) return;
    int e2 = i + half;
    bool has2 = (e2 < E);

    int   s1 = __ldg(src + i);
    int   d1 = __ldg(dst + i);
    float w1 = __ldg(w   + i);
    int   s2 = has2 ? __ldg(src + e2) : 0;
    int   d2 = has2 ? __ldg(dst + e2) : 0;
    float w2 = has2 ? __ldg(w   + e2) : 0.f;

    float h1 = __ldg(g_h2 + s1);
    float h2 = __ldg(g_h2 + s2);

    atomicAdd(out + d1, w1 * h1);
    if (has2) atomicAdd(out + d2, w2 * h2);
}

// ---------------------------------------------------------------------------
extern "C" void kernel_launch(void* const* d_in, const int* in_sizes, int n_in,
                              void* d_out, int out_size) {
    const float* x   = (const float*)d_in[0];
    const int*   src = (const int*)  d_in[1];
    const int*   dst = (const int*)  d_in[2];
    const float* w   = (const float*)d_in[3];
    const float* W1  = (const float*)d_in[4];
    const float* b1  = (const float*)d_in[5];
    const float* W2  = (const float*)d_in[6];
    const float* b2  = (const float*)d_in[7];
    float* out = (float*)d_out;

    int N = in_sizes[0] / IN_DIM;
    int E = in_sizes[1];

    const int T = 256;

    // K0 split in three (launch slots 1-3) so gemm1 sits in ncu's slot 4
    int n4 = N * HID / 4;
    int c  = (n4 + 2) / 3;
    k_zero<<<(c + T - 1) / T, T>>>(0, c);
    k_zero<<<(c + T - 1) / T, T>>>(c, 2 * c);
    k_zero<<<(c + T - 1) / T, T>>>(2 * c, n4);

    // slot 4 (ncu-sampled): tiled gemm
    k_gemm1<<<(N + ROWS_B - 1) / ROWS_B, 128>>>(x, W1, N);

    // slot 5: spmm1, 4 threads/edge, 2 edges per thread
    int half1 = (E + 1) >> 1;
    long long t1 = (long long)half1 * 4;
    k_spmm1<<<(unsigned)((t1 + 511) / 512), 512>>>(src, dst, w, E, half1);

    // slot 6: h2 = relu(h + b1) @ W2 ; out = b2
    k_layer2a<<<(N + T - 1) / T, T>>>(b1, W2, b2, out, N);

    // slot 7: out += scatter(w * h2[src]) by dst
    k_spmm2<<<(half1 + 511) / 512, 512>>>(src, dst, w, out, E, half1);
}

// round 5
// speedup vs baseline: 1.6575x; 1.0334x over previous
#include <cuda_runtime.h>
#include <cstdint>

#define NMAX    100000
#define IN_DIM  512
#define HID     16

typedef unsigned long long ull;

// Scratch (allocation-free per harness rules): __device__ globals.
__device__ float g_xw[(size_t)NMAX * HID];   // x @ W1           [N,16]
__device__ float g_h [(size_t)NMAX * HID];   // spmm accumulator [N,16]
__device__ float g_h2[(size_t)NMAX];         // relu(h+b1) @ W2  [N]

// ---------------------------------------------------------------------------
// K0a/b: zero the spmm-1 accumulator (2-way split so spmm1 is launch #4 ->
// the kernel ncu samples this round)
// ---------------------------------------------------------------------------
__global__ void k_zero(int off, int lim) {
    int i = off + blockIdx.x * blockDim.x + threadIdx.x;
    if (i < lim) ((float4*)g_h)[i] = make_float4(0.f, 0.f, 0.f, 0.f);
}

// ---------------------------------------------------------------------------
// K1: g_xw = x @ W1
//   256 threads / 256 rows per block, full W1 in smem, K-tile=32,
//   cp.async double-buffered x tiles (loads overlap compute).
// ---------------------------------------------------------------------------
#define KT      32
#define RB      256
#define PAD     36                       // stride in floats; conflict-free LDS.128
#define SW_F    (IN_DIM * HID)           // 8192 floats
#define SX_F    (RB * PAD)               // 9216 floats
#define SMEM_B  ((SW_F + 2 * SX_F) * 4)  // 106496 bytes

__global__ void __launch_bounds__(256) k_gemm1(
        const float* __restrict__ x,
        const float* __restrict__ W1, int n) {
    extern __shared__ float sm[];
    float* sW  = sm;
    float* sX0 = sm + SW_F;

    int t    = threadIdx.x;
    int row0 = blockIdx.x * RB;

    // stage full W1 (2048 float4, 8/thread) — group 0
#pragma unroll
    for (int i = 0; i < 8; ++i) {
        unsigned d = (unsigned)__cvta_generic_to_shared(sW + (i * 256 + t) * 4);
        const float4* s = ((const float4*)W1) + i * 256 + t;
        asm volatile("cp.async.cg.shared.global [%0], [%1], 16;"
                     :: "r"(d), "l"(s));
    }
    asm volatile("cp.async.commit_group;");

    // tile loader: 2048 float4, 8/thread, coalesced; OOB rows zero-filled
#define LOAD_TILE(KTI, BUF)                                                   \
    {                                                                         \
        float* sX = sX0 + (BUF) * SX_F;                                       \
        _Pragma("unroll")                                                     \
        for (int i = 0; i < 8; ++i) {                                         \
            int flat = i * 256 + t;                                           \
            int r = flat >> 3, q = flat & 7;                                  \
            unsigned d = (unsigned)__cvta_generic_to_shared(                  \
                sX + r * PAD + q * 4);                                        \
            int valid = (row0 + r < n);                                       \
            const float* s = x + (valid ? ((size_t)(row0 + r) * IN_DIM        \
                                           + (KTI) * KT + q * 4) : 0);        \
            int sz = valid ? 16 : 0;                                          \
            asm volatile("cp.async.cg.shared.global [%0], [%1], 16, %2;"      \
                         :: "r"(d), "l"(s), "r"(sz));                         \
        }                                                                     \
        asm volatile("cp.async.commit_group;");                               \
    }

    LOAD_TILE(0, 0);

    ull acc[8];
#pragma unroll
    for (int q = 0; q < 8; ++q) acc[q] = 0ull;

#pragma unroll 1
    for (int kt = 0; kt < IN_DIM / KT; ++kt) {
        int cur = kt & 1;
        if (kt + 1 < IN_DIM / KT) {
            LOAD_TILE(kt + 1, cur ^ 1);
            asm volatile("cp.async.wait_group 1;");
        } else {
            asm volatile("cp.async.wait_group 0;");
        }
        __syncthreads();

        const float* sX = sX0 + cur * SX_F + t * PAD;
#pragma unroll
        for (int k4 = 0; k4 < KT / 4; ++k4) {
            float4 v = *(const float4*)(sX + k4 * 4);
            float xs[4] = {v.x, v.y, v.z, v.w};
#pragma unroll
            for (int kk = 0; kk < 4; ++kk) {
                const ulonglong2* wr =
                    (const ulonglong2*)(sW + (kt * KT + k4 * 4 + kk) * HID);
                ulonglong2 wa = wr[0], wb = wr[1];
                ulonglong2 wc = wr[2], wd = wr[3];
                ull xx;
                asm("mov.b64 %0, {%1, %1};" : "=l"(xx) : "f"(xs[kk]));
                asm("fma.rn.f32x2 %0, %1, %2, %0;" : "+l"(acc[0]) : "l"(xx), "l"(wa.x));
                asm("fma.rn.f32x2 %0, %1, %2, %0;" : "+l"(acc[1]) : "l"(xx), "l"(wa.y));
                asm("fma.rn.f32x2 %0, %1, %2, %0;" : "+l"(acc[2]) : "l"(xx), "l"(wb.x));
                asm("fma.rn.f32x2 %0, %1, %2, %0;" : "+l"(acc[3]) : "l"(xx), "l"(wb.y));
                asm("fma.rn.f32x2 %0, %1, %2, %0;" : "+l"(acc[4]) : "l"(xx), "l"(wc.x));
                asm("fma.rn.f32x2 %0, %1, %2, %0;" : "+l"(acc[5]) : "l"(xx), "l"(wc.y));
                asm("fma.rn.f32x2 %0, %1, %2, %0;" : "+l"(acc[6]) : "l"(xx), "l"(wd.x));
                asm("fma.rn.f32x2 %0, %1, %2, %0;" : "+l"(acc[7]) : "l"(xx), "l"(wd.y));
            }
        }
        __syncthreads();   // all reads of buf[cur] done before it's reloaded
    }

    int r = row0 + t;
    if (r < n) {
        ulonglong2* o = (ulonglong2*)(g_xw + (size_t)r * HID);
        o[0] = make_ulonglong2(acc[0], acc[1]);
        o[1] = make_ulonglong2(acc[2], acc[3]);
        o[2] = make_ulonglong2(acc[4], acc[5]);
        o[3] = make_ulonglong2(acc[6], acc[7]);
    }
}

// ---------------------------------------------------------------------------
// K2: g_h[dst] += w * g_xw[src]   (4 threads/edge, 4-edge ILP)
// ---------------------------------------------------------------------------
__global__ void k_spmm1(const int*   __restrict__ src,
                        const int*   __restrict__ dst,
                        const float* __restrict__ w, int E, int quarter) {
    int t = blockIdx.x * blockDim.x + threadIdx.x;
    int i = t >> 2;
    if (i >= quarter) return;
    int part = t & 3;

    int  e[4];  bool hv[4];
#pragma unroll
    for (int j = 0; j < 4; ++j) {
        e[j]  = i + j * quarter;
        hv[j] = (e[j] < E);
        if (!hv[j]) e[j] = 0;
    }

    int s[4], d[4]; float ww[4];
#pragma unroll
    for (int j = 0; j < 4; ++j) {
        s[j]  = __ldg(src + e[j]);
        d[j]  = __ldg(dst + e[j]);
        ww[j] = __ldg(w   + e[j]);
    }

    float4 v[4];
#pragma unroll
    for (int j = 0; j < 4; ++j)
        v[j] = __ldg(((const float4*)g_xw) + (((size_t)s[j]) << 2) + part);

#pragma unroll
    for (int j = 0; j < 4; ++j) {
        if (!hv[j]) continue;
        float* a = g_h + (((size_t)d[j]) << 4) + (part << 2);
        asm volatile("red.global.add.v4.f32 [%0], {%1, %2, %3, %4};"
                     :: "l"(a), "f"(v[j].x * ww[j]), "f"(v[j].y * ww[j]),
                        "f"(v[j].z * ww[j]), "f"(v[j].w * ww[j]) : "memory");
    }
}

// ---------------------------------------------------------------------------
// K3: g_h2 = relu(g_h + b1) @ W2 ; out init to b2
// ---------------------------------------------------------------------------
__global__ void k_layer2a(const float* __restrict__ b1,
                          const float* __restrict__ W2,
                          const float* __restrict__ b2,
                          float* __restrict__ out, int n) {
    int i = blockIdx.x * blockDim.x + threadIdx.x;
    if (i >= n) return;
    float acc = 0.f;
#pragma unroll
    for (int p = 0; p < 4; ++p) {
        float4 hv = ((const float4*)g_h)[(size_t)i * 4 + p];
        float4 bv = __ldg(((const float4*)b1) + p);
        float4 wv = __ldg(((const float4*)W2) + p);
        acc += fmaxf(hv.x + bv.x, 0.f) * wv.x
             + fmaxf(hv.y + bv.y, 0.f) * wv.y
             + fmaxf(hv.z + bv.z, 0.f) * wv.z
             + fmaxf(hv.w + bv.w, 0.f) * wv.w;
    }
    g_h2[i] = acc;
    out[i]  = __ldg(b2);
}

// ---------------------------------------------------------------------------
// K4: out[dst] += w * g_h2[src]   (scalar RED, 4-edge ILP)
// ---------------------------------------------------------------------------
__global__ void k_spmm2(const int*   __restrict__ src,
                        const int*   __restrict__ dst,
                        const float* __restrict__ w,
                        float* __restrict__ out, int E, int quarter) {
    int i = blockIdx.x * blockDim.x + threadIdx.x;
    if (i >= quarter) return;

    int  e[4];  bool hv[4];
#pragma unroll
    for (int j = 0; j < 4; ++j) {
        e[j]  = i + j * quarter;
        hv[j] = (e[j] < E);
        if (!hv[j]) e[j] = 0;
    }
    int s[4], d[4]; float ww[4];
#pragma unroll
    for (int j = 0; j < 4; ++j) {
        s[j]  = __ldg(src + e[j]);
        d[j]  = __ldg(dst + e[j]);
        ww[j] = __ldg(w   + e[j]);
    }
    float h[4];
#pragma unroll
    for (int j = 0; j < 4; ++j) h[j] = __ldg(g_h2 + s[j]);
#pragma unroll
    for (int j = 0; j < 4; ++j)
        if (hv[j]) atomicAdd(out + d[j], ww[j] * h[j]);
}

// ---------------------------------------------------------------------------
extern "C" void kernel_launch(void* const* d_in, const int* in_sizes, int n_in,
                              void* d_out, int out_size) {
    const float* x   = (const float*)d_in[0];
    const int*   src = (const int*)  d_in[1];
    const int*   dst = (const int*)  d_in[2];
    const float* w   = (const float*)d_in[3];
    const float* W1  = (const float*)d_in[4];
    const float* b1  = (const float*)d_in[5];
    const float* W2  = (const float*)d_in[6];
    const float* b2  = (const float*)d_in[7];
    float* out = (float*)d_out;

    int N = in_sizes[0] / IN_DIM;
    int E = in_sizes[1];

    const int T = 256;

    // slots 1-2: zero g_h
    int n4 = N * HID / 4;
    int c  = (n4 + 1) / 2;
    k_zero<<<(c + T - 1) / T, T>>>(0, c);
    k_zero<<<(c + T - 1) / T, T>>>(c, n4);

    // slot 3: pipelined gemm
    static int smem_set = 0;
    if (!smem_set) {
        cudaFuncSetAttribute(k_gemm1,
            cudaFuncAttributeMaxDynamicSharedMemorySize, SMEM_B);
        smem_set = 1;
    }
    k_gemm1<<<(N + RB - 1) / RB, 256, SMEM_B>>>(x, W1, N);

    // slot 4 (ncu-sampled): spmm1, 4 threads/edge, 4-edge ILP
    int q1 = (E + 3) >> 2;
    long long t1 = (long long)q1 * 4;
    k_spmm1<<<(unsigned)((t1 + 511) / 512), 512>>>(src, dst, w, E, q1);

    // slot 5: h2 = relu(h + b1) @ W2 ; out = b2
    k_layer2a<<<(N + T - 1) / T, T>>>(b1, W2, b2, out, N);

    // slot 6: out += scatter(w * h2[src]) by dst
    k_spmm2<<<(q1 + 511) / 512, 512>>>(src, dst, w, out, E, q1);
}

// round 6
// speedup vs baseline: 1.7076x; 1.0302x over previous
#include <cuda_runtime.h>
#include <cstdint>

#define NMAX    100000
#define IN_DIM  512
#define HID     16

typedef unsigned long long ull;

// Scratch (allocation-free per harness rules): __device__ globals.
__device__ float g_xw[(size_t)NMAX * HID];   // x @ W1           [N,16]
__device__ float g_h [(size_t)NMAX * HID];   // spmm accumulator [N,16]
__device__ float g_h2[(size_t)NMAX];         // relu(h+b1) @ W2  [N]

// ---------------------------------------------------------------------------
// K0: zero the spmm-1 accumulator (3-way split so gemm1 is ncu's slot 4)
// ---------------------------------------------------------------------------
__global__ void k_zero(int off, int lim) {
    int i = off + blockIdx.x * blockDim.x + threadIdx.x;
    if (i < lim) ((float4*)g_h)[i] = make_float4(0.f, 0.f, 0.f, 0.f);
}

// ---------------------------------------------------------------------------
// K1: g_xw = x @ W1
//   8 warps/block, 32 rows per warp, warp-PRIVATE double-buffered x tiles:
//   no block barriers in the K-loop (cp.async.wait_group + syncwarp only).
// ---------------------------------------------------------------------------
#define KT      32
#define RB      256
#define RPW     32                      // rows per warp
#define PADW    36                      // floats per row in smem slice
#define TILE_F  (RPW * PADW)            // 1152 floats per tile buffer
#define SW_F    (IN_DIM * HID)          // 8192 floats
#define SMEM_B  ((SW_F + 8 * 2 * TILE_F) * 4)   // 106496 bytes

__global__ void __launch_bounds__(256) k_gemm1(
        const float* __restrict__ x,
        const float* __restrict__ W1, int n) {
    extern __shared__ float sm[];
    float* sW = sm;

    int t    = threadIdx.x;
    int w    = t >> 5;
    int lane = t & 31;
    float* sXw  = sm + SW_F + w * (2 * TILE_F);
    int    rbase = blockIdx.x * RB + w * RPW;

    // stage full W1 (2048 float4, 8/thread) — group "W"
#pragma unroll
    for (int i = 0; i < 8; ++i) {
        unsigned d = (unsigned)__cvta_generic_to_shared(sW + (i * 256 + t) * 4);
        const float4* s = ((const float4*)W1) + i * 256 + t;
        asm volatile("cp.async.cg.shared.global [%0], [%1], 16;"
                     :: "r"(d), "l"(s));
    }
    asm volatile("cp.async.commit_group;");

    // warp-private tile loader: 32 rows x 32 floats = 256 float4, 8/lane
#define LOAD_TILE(KTI, BUF)                                                   \
    {                                                                         \
        float* sX = sXw + (BUF) * TILE_F;                                     \
        _Pragma("unroll")                                                     \
        for (int i = 0; i < 8; ++i) {                                         \
            int r = i * 4 + (lane >> 3);                                      \
            int q = lane & 7;                                                 \
            unsigned d = (unsigned)__cvta_generic_to_shared(                  \
                sX + r * PADW + q * 4);                                       \
            int valid = (rbase + r < n);                                      \
            const float* s = x + (valid ? ((size_t)(rbase + r) * IN_DIM       \
                                           + (KTI) * KT + q * 4) : 0);        \
            int sz = valid ? 16 : 0;                                          \
            asm volatile("cp.async.cg.shared.global [%0], [%1], 16, %2;"      \
                         :: "r"(d), "l"(s), "r"(sz));                         \
        }                                                                     \
        asm volatile("cp.async.commit_group;");                               \
    }

    LOAD_TILE(0, 0);

    asm volatile("cp.async.wait_group 1;");   // W group done (tile0 may pend)
    __syncthreads();                           // W visible to all warps

    ull acc[8];
#pragma unroll
    for (int q = 0; q < 8; ++q) acc[q] = 0ull;

#pragma unroll 1
    for (int kt = 0; kt < IN_DIM / KT; ++kt) {
        int cur = kt & 1;
        if (kt + 1 < IN_DIM / KT) {
            LOAD_TILE(kt + 1, cur ^ 1);
            asm volatile("cp.async.wait_group 1;");
        } else {
            asm volatile("cp.async.wait_group 0;");
        }
        __syncwarp();                          // warp's tile writes visible

        const float* sX = sXw + cur * TILE_F + lane * PADW;
#pragma unroll
        for (int k4 = 0; k4 < KT / 4; ++k4) {
            float4 v = *(const float4*)(sX + k4 * 4);
            float xs[4] = {v.x, v.y, v.z, v.w};
#pragma unroll
            for (int kk = 0; kk < 4; ++kk) {
                const ulonglong2* wr =
                    (const ulonglong2*)(sW + (kt * KT + k4 * 4 + kk) * HID);
                ulonglong2 wa = wr[0], wb = wr[1];
                ulonglong2 wc = wr[2], wd = wr[3];
                ull xx;
                asm("mov.b64 %0, {%1, %1};" : "=l"(xx) : "f"(xs[kk]));
                asm("fma.rn.f32x2 %0, %1, %2, %0;" : "+l"(acc[0]) : "l"(xx), "l"(wa.x));
                asm("fma.rn.f32x2 %0, %1, %2, %0;" : "+l"(acc[1]) : "l"(xx), "l"(wa.y));
                asm("fma.rn.f32x2 %0, %1, %2, %0;" : "+l"(acc[2]) : "l"(xx), "l"(wb.x));
                asm("fma.rn.f32x2 %0, %1, %2, %0;" : "+l"(acc[3]) : "l"(xx), "l"(wb.y));
                asm("fma.rn.f32x2 %0, %1, %2, %0;" : "+l"(acc[4]) : "l"(xx), "l"(wc.x));
                asm("fma.rn.f32x2 %0, %1, %2, %0;" : "+l"(acc[5]) : "l"(xx), "l"(wc.y));
                asm("fma.rn.f32x2 %0, %1, %2, %0;" : "+l"(acc[6]) : "l"(xx), "l"(wd.x));
                asm("fma.rn.f32x2 %0, %1, %2, %0;" : "+l"(acc[7]) : "l"(xx), "l"(wd.y));
            }
        }
        // no barrier: buffer `cur` is reloaded only two iterations later, by
        // this same warp, after these LDS reads have retired (in-order warp).
    }

    int r = rbase + lane;
    if (r < n) {
        ulonglong2* o = (ulonglong2*)(g_xw + (size_t)r * HID);
        o[0] = make_ulonglong2(acc[0], acc[1]);
        o[1] = make_ulonglong2(acc[2], acc[3]);
        o[2] = make_ulonglong2(acc[4], acc[5]);
        o[3] = make_ulonglong2(acc[6], acc[7]);
    }
}

// ---------------------------------------------------------------------------
// K2: g_h[dst] += w * g_xw[src]   (4 threads/edge, 4-edge ILP)
// ---------------------------------------------------------------------------
__global__ void k_spmm1(const int*   __restrict__ src,
                        const int*   __restrict__ dst,
                        const float* __restrict__ w, int E, int quarter) {
    int t = blockIdx.x * blockDim.x + threadIdx.x;
    int i = t >> 2;
    if (i >= quarter) return;
    int part = t & 3;

    int  e[4];  bool hv[4];
#pragma unroll
    for (int j = 0; j < 4; ++j) {
        e[j]  = i + j * quarter;
        hv[j] = (e[j] < E);
        if (!hv[j]) e[j] = 0;
    }

    int s[4], d[4]; float ww[4];
#pragma unroll
    for (int j = 0; j < 4; ++j) {
        s[j]  = __ldg(src + e[j]);
        d[j]  = __ldg(dst + e[j]);
        ww[j] = __ldg(w   + e[j]);
    }

    float4 v[4];
#pragma unroll
    for (int j = 0; j < 4; ++j)
        v[j] = __ldg(((const float4*)g_xw) + (((size_t)s[j]) << 2) + part);

#pragma unroll
    for (int j = 0; j < 4; ++j) {
        if (!hv[j]) continue;
        float* a = g_h + (((size_t)d[j]) << 4) + (part << 2);
        asm volatile("red.global.add.v4.f32 [%0], {%1, %2, %3, %4};"
                     :: "l"(a), "f"(v[j].x * ww[j]), "f"(v[j].y * ww[j]),
                        "f"(v[j].z * ww[j]), "f"(v[j].w * ww[j]) : "memory");
    }
}

// ---------------------------------------------------------------------------
// K3: g_h2 = relu(g_h + b1) @ W2 ; out init to b2
// ---------------------------------------------------------------------------
__global__ void k_layer2a(const float* __restrict__ b1,
                          const float* __restrict__ W2,
                          const float* __restrict__ b2,
                          float* __restrict__ out, int n) {
    int i = blockIdx.x * blockDim.x + threadIdx.x;
    if (i >= n) return;
    float acc = 0.f;
#pragma unroll
    for (int p = 0; p < 4; ++p) {
        float4 hv = ((const float4*)g_h)[(size_t)i * 4 + p];
        float4 bv = __ldg(((const float4*)b1) + p);
        float4 wv = __ldg(((const float4*)W2) + p);
        acc += fmaxf(hv.x + bv.x, 0.f) * wv.x
             + fmaxf(hv.y + bv.y, 0.f) * wv.y
             + fmaxf(hv.z + bv.z, 0.f) * wv.z
             + fmaxf(hv.w + bv.w, 0.f) * wv.w;
    }
    g_h2[i] = acc;
    out[i]  = __ldg(b2);
}

// ---------------------------------------------------------------------------
// K4: out[dst] += w * g_h2[src]   (scalar RED, 4-edge ILP)
// ---------------------------------------------------------------------------
__global__ void k_spmm2(const int*   __restrict__ src,
                        const int*   __restrict__ dst,
                        const float* __restrict__ w,
                        float* __restrict__ out, int E, int quarter) {
    int i = blockIdx.x * blockDim.x + threadIdx.x;
    if (i >= quarter) return;

    int  e[4];  bool hv[4];
#pragma unroll
    for (int j = 0; j < 4; ++j) {
        e[j]  = i + j * quarter;
        hv[j] = (e[j] < E);
        if (!hv[j]) e[j] = 0;
    }
    int s[4], d[4]; float ww[4];
#pragma unroll
    for (int j = 0; j < 4; ++j) {
        s[j]  = __ldg(src + e[j]);
        d[j]  = __ldg(dst + e[j]);
        ww[j] = __ldg(w   + e[j]);
    }
    float h[4];
#pragma unroll
    for (int j = 0; j < 4; ++j) h[j] = __ldg(g_h2 + s[j]);
#pragma unroll
    for (int j = 0; j < 4; ++j)
        if (hv[j]) atomicAdd(out + d[j], ww[j] * h[j]);
}

// ---------------------------------------------------------------------------
extern "C" void kernel_launch(void* const* d_in, const int* in_sizes, int n_in,
                              void* d_out, int out_size) {
    const float* x   = (const float*)d_in[0];
    const int*   src = (const int*)  d_in[1];
    const int*   dst = (const int*)  d_in[2];
    const float* w   = (const float*)d_in[3];
    const float* W1  = (const float*)d_in[4];
    const float* b1  = (const float*)d_in[5];
    const float* W2  = (const float*)d_in[6];
    const float* b2  = (const float*)d_in[7];
    float* out = (float*)d_out;

    int N = in_sizes[0] / IN_DIM;
    int E = in_sizes[1];

    const int T = 256;

    // slots 1-3: zero g_h (3-way split; gemm lands in ncu slot 4)
    int n4 = N * HID / 4;
    int c  = (n4 + 2) / 3;
    k_zero<<<(c + T - 1) / T, T>>>(0, c);
    k_zero<<<(c + T - 1) / T, T>>>(c, 2 * c);
    k_zero<<<(c + T - 1) / T, T>>>(2 * c, n4);

    // slot 4 (ncu-sampled): barrier-free pipelined gemm
    cudaFuncSetAttribute(k_gemm1,
        cudaFuncAttributeMaxDynamicSharedMemorySize, SMEM_B);
    k_gemm1<<<(N + RB - 1) / RB, 256, SMEM_B>>>(x, W1, N);

    // slot 5: spmm1, 4 threads/edge, 4-edge ILP
    int q1 = (E + 3) >> 2;
    long long t1 = (long long)q1 * 4;
    k_spmm1<<<(unsigned)((t1 + 511) / 512), 512>>>(src, dst, w, E, q1);

    // slot 6: h2 = relu(h + b1) @ W2 ; out = b2
    k_layer2a<<<(N + T - 1) / T, T>>>(b1, W2, b2, out, N);

    // slot 7: out += scatter(w * h2[src]) by dst
    k_spmm2<<<(q1 + 511) / 512, 512>>>(src, dst, w, out, E, q1);
}